// round 11
// baseline (speedup 1.0000x reference)
#include <cuda_runtime.h>
#include <cuda_fp16.h>
#include <stdint.h>
#include <math.h>

// Problem constants (fixed by setup_inputs)
#define BATCH 2
#define S_TOT 21760
#define DIM 256
#define NHEAD 8
#define NLVL 4
#define NPT 4
#define DFF 1024
#define DHEAD 32
#define M_TOK (BATCH * S_TOT)   // 43520 rows

// ---------------------------------------------------------------------------
// Scratch (device globals — no runtime allocation allowed)
// ---------------------------------------------------------------------------
__device__ float g_q     [M_TOK * DIM];
__device__ __half g_val  [M_TOK * DIM];   // fp16 value tensor
__device__ float g_oa    [M_TOK * 384];   // merged offsets(256) + attn logits(128)
__device__ float g_acc   [M_TOK * DIM];
__device__ float g_y     [M_TOK * DIM];
__device__ float g_x     [M_TOK * DIM];
__device__ float g_ffn   [M_TOK * DFF];
__device__ float g_y2    [M_TOK * DIM];

// Transposed (K-major), tf32-pre-rounded weights: WT[n*K + k] = tf32(W[k*N + n])
__device__ float g_WT_val [DIM * DIM];
__device__ float g_WT_oa  [384 * DIM];
__device__ float g_WT_out [DIM * DIM];
__device__ float g_WT_f1  [DFF * DIM];
__device__ float g_WT_f2  [DIM * DFF];
__device__ float g_b_oa   [384];

__device__ __forceinline__ uint32_t f2tf32(float f) {
    uint32_t u;
    asm("cvt.rna.tf32.f32 %0, %1;" : "=r"(u) : "f"(f));
    return u;
}

__device__ __forceinline__ uint32_t smem_u32(const void* p) {
    uint32_t a;
    asm("{ .reg .u64 t; cvta.to.shared.u64 t, %1; cvt.u32.u64 %0, t; }"
        : "=r"(a) : "l"(p));
    return a;
}

// ---------------------------------------------------------------------------
// One launch: all weight transposes (with tf32 pre-round) + bias concat.
// ---------------------------------------------------------------------------
__global__ void transpose_all_kernel(
    const float* __restrict__ W_val, const float* __restrict__ W_off,
    const float* __restrict__ W_attn, const float* __restrict__ W_out,
    const float* __restrict__ W_f1,  const float* __restrict__ W_f2,
    const float* __restrict__ b_off, const float* __restrict__ b_attn)
{
    const int bid = blockIdx.x;
    const int tx = threadIdx.x, ty0 = threadIdx.y;

    if (bid >= 736) {   // bias concat blocks (736, 737)
        int idx = (bid - 736) * 256 + ty0 * 32 + tx;
        if (idx < 384)
            g_b_oa[idx] = (idx < 256) ? b_off[idx] : b_attn[idx - 256];
        return;
    }

    const float* W; float* WT; int K, N, lt;
    if      (bid < 64)  { W = W_val;  WT = g_WT_val;            K = 256;  N = 256;  lt = bid; }
    else if (bid < 128) { W = W_off;  WT = g_WT_oa;             K = 256;  N = 256;  lt = bid - 64; }
    else if (bid < 160) { W = W_attn; WT = g_WT_oa + 256 * 256; K = 256;  N = 128;  lt = bid - 128; }
    else if (bid < 224) { W = W_out;  WT = g_WT_out;            K = 256;  N = 256;  lt = bid - 160; }
    else if (bid < 480) { W = W_f1;   WT = g_WT_f1;             K = 256;  N = 1024; lt = bid - 224; }
    else                { W = W_f2;   WT = g_WT_f2;             K = 1024; N = 256;  lt = bid - 480; }

    const int tiles_x = N >> 5;
    const int bn = (lt % tiles_x) * 32;
    const int bk = (lt / tiles_x) * 32;

    __shared__ float tile[32][33];
#pragma unroll
    for (int i = 0; i < 4; i++) {
        int ty = ty0 + i * 8;
        tile[ty][tx] = W[(size_t)(bk + ty) * N + bn + tx];
    }
    __syncthreads();
#pragma unroll
    for (int i = 0; i < 4; i++) {
        int ty = ty0 + i * 8;
        WT[(size_t)(bn + ty) * K + bk + tx] =
            __uint_as_float(f2tf32(tile[tx][ty]));
    }
}

// ---------------------------------------------------------------------------
// tf32 mma.sync GEMM, cp.async 4-stage pipeline, one barrier per chunk.
// C[M,N] = A[M,K] @ WT[N,K]^T + bias (+relu / +res / fp16-out)
// BM=BN=128, BK=16, 256 threads (8 warps, 2x4), warp tile 64x32.
// A is implicitly truncated to tf32 by HMMA (RZ); WT pre-rounded RNA.
// fuse: 0 none, 1 relu, 2 residual add, 3 write fp16
// ---------------------------------------------------------------------------
#define BKC 16
#define SMS 20   // smem row stride (floats): conflict-free for frag patterns
#define STG 4
#define BUF (128 * SMS)

__global__ __launch_bounds__(256) void gemm_tc_kernel(
    const float* __restrict__ A, const float* __restrict__ WT,
    const float* __restrict__ bias, const float* __restrict__ res,
    float* __restrict__ C, int M, int N, int K, int fuse)
{
    extern __shared__ float smem[];
    float* sA = smem;               // STG * BUF floats
    float* sB = smem + STG * BUF;   // STG * BUF floats

    const int t    = threadIdx.x;
    const int wid  = t >> 5;
    const int lane = t & 31;
    const int wm   = (wid >> 2) * 64;
    const int wn   = (wid & 3) * 32;
    const int bm   = blockIdx.y * 128;
    const int bn   = blockIdx.x * 128;

    // copy units: 512 x 16B per operand tile; thread t does units t and t+256
    const int r0 = t >> 2,         s0 = (t & 3) << 2;
    const int r1 = (t + 256) >> 2, s1 = ((t + 256) & 3) << 2;

    const float* Ab = A  + (size_t)bm * K;
    const float* Bb = WT + (size_t)bn * K;

    float acc[4][4][4];
#pragma unroll
    for (int i = 0; i < 4; i++)
#pragma unroll
        for (int j = 0; j < 4; j++)
#pragma unroll
            for (int e = 0; e < 4; e++) acc[i][j][e] = 0.f;

    const int nch = K >> 4;

    auto issue = [&](int c) {
        const int s = c % STG;
        float* a = sA + s * BUF;
        float* b = sB + s * BUF;
        const int kb = c << 4;
        uint32_t d;
        d = smem_u32(a + r0 * SMS + s0);
        asm volatile("cp.async.ca.shared.global [%0], [%1], 16;"
                     :: "r"(d), "l"(Ab + (size_t)r0 * K + kb + s0) : "memory");
        d = smem_u32(a + r1 * SMS + s1);
        asm volatile("cp.async.ca.shared.global [%0], [%1], 16;"
                     :: "r"(d), "l"(Ab + (size_t)r1 * K + kb + s1) : "memory");
        d = smem_u32(b + r0 * SMS + s0);
        asm volatile("cp.async.ca.shared.global [%0], [%1], 16;"
                     :: "r"(d), "l"(Bb + (size_t)r0 * K + kb + s0) : "memory");
        d = smem_u32(b + r1 * SMS + s1);
        asm volatile("cp.async.ca.shared.global [%0], [%1], 16;"
                     :: "r"(d), "l"(Bb + (size_t)r1 * K + kb + s1) : "memory");
        asm volatile("cp.async.commit_group;" ::: "memory");
    };

    const int lr = lane >> 2;   // 0..7
    const int lk = lane & 3;    // 0..3

    auto compute = [&](int c) {
        const int s = c % STG;
        const float* a  = sA + s * BUF;
        const float* bp = sB + s * BUF;
#pragma unroll
        for (int ks = 0; ks < BKC; ks += 8) {
            uint32_t af[4][4], bf[4][2];
#pragma unroll
            for (int mt = 0; mt < 4; mt++) {
                int mr = wm + mt * 16 + lr;
                af[mt][0] = __float_as_uint(a[mr * SMS + ks + lk]);
                af[mt][1] = __float_as_uint(a[(mr + 8) * SMS + ks + lk]);
                af[mt][2] = __float_as_uint(a[mr * SMS + ks + lk + 4]);
                af[mt][3] = __float_as_uint(a[(mr + 8) * SMS + ks + lk + 4]);
            }
#pragma unroll
            for (int nt = 0; nt < 4; nt++) {
                int nc = wn + nt * 8 + lr;
                bf[nt][0] = __float_as_uint(bp[nc * SMS + ks + lk]);
                bf[nt][1] = __float_as_uint(bp[nc * SMS + ks + lk + 4]);
            }
#pragma unroll
            for (int mt = 0; mt < 4; mt++)
#pragma unroll
                for (int nt = 0; nt < 4; nt++) {
                    asm volatile(
                        "mma.sync.aligned.m16n8k8.row.col.f32.tf32.tf32.f32 "
                        "{%0,%1,%2,%3}, {%4,%5,%6,%7}, {%8,%9}, {%0,%1,%2,%3};"
                        : "+f"(acc[mt][nt][0]), "+f"(acc[mt][nt][1]),
                          "+f"(acc[mt][nt][2]), "+f"(acc[mt][nt][3])
                        : "r"(af[mt][0]), "r"(af[mt][1]),
                          "r"(af[mt][2]), "r"(af[mt][3]),
                          "r"(bf[nt][0]), "r"(bf[nt][1]));
                }
        }
    };

    issue(0);
    if (nch > 1) issue(1);
    if (nch > 2) issue(2);

    for (int c = 0; c < nch; c++) {
        asm volatile("cp.async.wait_group 2;" ::: "memory");
        __syncthreads();
        if (c + 3 < nch) issue(c + 3);
        compute(c);
    }

    // ---- epilogue ----
    const int cL = (lane & 3) * 2;
#pragma unroll
    for (int mt = 0; mt < 4; mt++) {
        int row = bm + wm + mt * 16 + lr;
#pragma unroll
        for (int nt = 0; nt < 4; nt++) {
            int col = bn + wn + nt * 8 + cL;
            float2 v0, v1;
            v0.x = acc[mt][nt][0] + bias[col];
            v0.y = acc[mt][nt][1] + bias[col + 1];
            v1.x = acc[mt][nt][2] + bias[col];
            v1.y = acc[mt][nt][3] + bias[col + 1];
            if (fuse == 1) {
                v0.x = fmaxf(v0.x, 0.f); v0.y = fmaxf(v0.y, 0.f);
                v1.x = fmaxf(v1.x, 0.f); v1.y = fmaxf(v1.y, 0.f);
            } else if (fuse == 2) {
                float2 r0v = *(const float2*)&res[(size_t)row * N + col];
                float2 r1v = *(const float2*)&res[(size_t)(row + 8) * N + col];
                v0.x += r0v.x; v0.y += r0v.y;
                v1.x += r1v.x; v1.y += r1v.y;
            }
            if (fuse == 3) {
                __half* Ch = (__half*)C;
                *(__half2*)&Ch[(size_t)row * N + col] =
                    __floats2half2_rn(v0.x, v0.y);
                *(__half2*)&Ch[(size_t)(row + 8) * N + col] =
                    __floats2half2_rn(v1.x, v1.y);
            } else {
                *(float2*)&C[(size_t)row * N + col] = v0;
                *(float2*)&C[(size_t)(row + 8) * N + col] = v1;
            }
        }
    }
}

// ---------------------------------------------------------------------------
// q = src + pos
// ---------------------------------------------------------------------------
__global__ void add4_kernel(const float4* __restrict__ a,
                            const float4* __restrict__ b,
                            float4* __restrict__ c, int n4) {
    int i = blockIdx.x * blockDim.x + threadIdx.x;
    if (i < n4) {
        float4 x = a[i], y = b[i];
        x.x += y.x; x.y += y.y; x.z += y.z; x.w += y.w;
        c[i] = x;
    }
}

// ---------------------------------------------------------------------------
// Deformable sampling with FUSED softmax, fp16 value tensor.
// One warp per (token, head); lane = channel (DH=32).
// ---------------------------------------------------------------------------
__global__ __launch_bounds__(256) void deform_sample_kernel(
    const __half* __restrict__ value, const float* __restrict__ oa,
    const float* __restrict__ refp, float* __restrict__ out)
{
    const int lane = threadIdx.x & 31;
    const int wid  = blockIdx.x * (blockDim.x >> 5) + (threadIdx.x >> 5);
    const int tok = wid >> 3;
    const int h   = wid & 7;
    const int b   = tok / S_TOT;

    float offv  = oa[(size_t)tok * 384 + h * 32 + lane];
    float logit = (lane < 16) ? oa[(size_t)tok * 384 + 256 + h * 16 + lane] : -1e30f;
    float refv  = (lane < 8)  ? refp[(size_t)tok * 8 + lane] : 0.f;

    // softmax over 16 logits held in lanes 0..15
    float m = logit;
#pragma unroll
    for (int o = 8; o > 0; o >>= 1) m = fmaxf(m, __shfl_xor_sync(0xffffffffu, m, o));
    float e = (lane < 16) ? expf(logit - m) : 0.f;
    float ssum = e;
#pragma unroll
    for (int o = 8; o > 0; o >>= 1) ssum += __shfl_xor_sync(0xffffffffu, ssum, o);
    float attnv = e / ssum;

    const __half* vbase = value + (size_t)b * S_TOT * 256 + h * 32 + lane;

    const int HW[4]     = {128, 64, 32, 16};
    const int starts[4] = {0, 16384, 20480, 21504};

    float acc = 0.f;
#pragma unroll
    for (int l = 0; l < 4; l++) {
        const int   Hl = HW[l], Wl = HW[l];
        const float fH = (float)Hl, fW = (float)Wl;
        float rx = __shfl_sync(0xffffffffu, refv, 2 * l);
        float ry = __shfl_sync(0xffffffffu, refv, 2 * l + 1);
        const __half* vlev = vbase + (size_t)starts[l] * 256;
#pragma unroll
        for (int p = 0; p < 4; p++) {
            int j = l * 4 + p;
            float ox = __shfl_sync(0xffffffffu, offv, 2 * j);
            float oy = __shfl_sync(0xffffffffu, offv, 2 * j + 1);
            float aw = __shfl_sync(0xffffffffu, attnv, j);

            float locx = rx + ox / fW;
            float locy = ry + oy / fH;
            float x = locx * fW - 0.5f;
            float y = locy * fH - 0.5f;
            float x0f = floorf(x), y0f = floorf(y);
            float wx = x - x0f, wy = y - y0f;
            int x0 = (int)x0f, y0 = (int)y0f;

            bool vx0 = (x0 >= 0) && (x0 < Wl);
            bool vx1 = (x0 + 1 >= 0) && (x0 + 1 < Wl);
            bool vy0 = (y0 >= 0) && (y0 < Hl);
            bool vy1 = (y0 + 1 >= 0) && (y0 + 1 < Hl);

            float samp = 0.f;
            if (vy0) {
                const __half* rowp = vlev + (size_t)(y0 * Wl) * 256;
                if (vx0) samp += (1.f - wx) * (1.f - wy) * __half2float(rowp[(size_t)x0 * 256]);
                if (vx1) samp += wx * (1.f - wy) * __half2float(rowp[(size_t)(x0 + 1) * 256]);
            }
            if (vy1) {
                const __half* rowp = vlev + (size_t)((y0 + 1) * Wl) * 256;
                if (vx0) samp += (1.f - wx) * wy * __half2float(rowp[(size_t)x0 * 256]);
                if (vx1) samp += wx * wy * __half2float(rowp[(size_t)(x0 + 1) * 256]);
            }
            acc += aw * samp;
        }
    }
    out[(size_t)tok * 256 + h * 32 + lane] = acc;
}

// ---------------------------------------------------------------------------
// LayerNorm over D=256: one warp per row.
// ---------------------------------------------------------------------------
__global__ __launch_bounds__(256) void ln_kernel(
    const float* __restrict__ in, const float* __restrict__ gamma,
    const float* __restrict__ beta, float* __restrict__ out, int rows)
{
    const int lane = threadIdx.x & 31;
    const int row  = blockIdx.x * 8 + (threadIdx.x >> 5);
    if (row >= rows) return;
    const float* p = in + (size_t)row * 256;

    float v[8];
    float s = 0.f;
#pragma unroll
    for (int i = 0; i < 8; i++) { v[i] = p[i * 32 + lane]; s += v[i]; }
#pragma unroll
    for (int o = 16; o > 0; o >>= 1) s += __shfl_xor_sync(0xffffffffu, s, o);
    float mu = s * (1.f / 256.f);

    float vs = 0.f;
#pragma unroll
    for (int i = 0; i < 8; i++) { float d = v[i] - mu; vs += d * d; }
#pragma unroll
    for (int o = 16; o > 0; o >>= 1) vs += __shfl_xor_sync(0xffffffffu, vs, o);
    float rstd = rsqrtf(vs * (1.f / 256.f) + 1e-5f);

    float* q = out + (size_t)row * 256;
#pragma unroll
    for (int i = 0; i < 8; i++) {
        int c = i * 32 + lane;
        q[c] = (v[i] - mu) * rstd * gamma[c] + beta[c];
    }
}

// ---------------------------------------------------------------------------
// Launch
// ---------------------------------------------------------------------------
extern "C" void kernel_launch(void* const* d_in, const int* in_sizes, int n_in,
                              void* d_out, int out_size) {
    const float* src    = (const float*)d_in[0];
    const float* pos    = (const float*)d_in[1];
    const float* refp   = (const float*)d_in[2];
    const float* W_off  = (const float*)d_in[5];
    const float* b_off  = (const float*)d_in[6];
    const float* W_attn = (const float*)d_in[7];
    const float* b_attn = (const float*)d_in[8];
    const float* W_val  = (const float*)d_in[9];
    const float* b_val  = (const float*)d_in[10];
    const float* W_out  = (const float*)d_in[11];
    const float* b_out  = (const float*)d_in[12];
    const float* W_f1   = (const float*)d_in[13];
    const float* b_f1   = (const float*)d_in[14];
    const float* W_f2   = (const float*)d_in[15];
    const float* b_f2   = (const float*)d_in[16];
    const float* ln1g   = (const float*)d_in[17];
    const float* ln1b   = (const float*)d_in[18];
    const float* ln2g   = (const float*)d_in[19];
    const float* ln2b   = (const float*)d_in[20];
    float* out = (float*)d_out;

    float *q, *oa, *acc, *y, *x, *ffn, *y2;
    __half* val;
    float *wtv, *wtoa, *wtu, *wt1, *wt2, *boa;
    cudaGetSymbolAddress((void**)&q,    g_q);
    cudaGetSymbolAddress((void**)&val,  g_val);
    cudaGetSymbolAddress((void**)&oa,   g_oa);
    cudaGetSymbolAddress((void**)&acc,  g_acc);
    cudaGetSymbolAddress((void**)&y,    g_y);
    cudaGetSymbolAddress((void**)&x,    g_x);
    cudaGetSymbolAddress((void**)&ffn,  g_ffn);
    cudaGetSymbolAddress((void**)&y2,   g_y2);
    cudaGetSymbolAddress((void**)&wtv,  g_WT_val);
    cudaGetSymbolAddress((void**)&wtoa, g_WT_oa);
    cudaGetSymbolAddress((void**)&wtu,  g_WT_out);
    cudaGetSymbolAddress((void**)&wt1,  g_WT_f1);
    cudaGetSymbolAddress((void**)&wt2,  g_WT_f2);
    cudaGetSymbolAddress((void**)&boa,  g_b_oa);

    const int DYN = STG * BUF * 2 * 4;   // 81920 B
    cudaFuncSetAttribute(gemm_tc_kernel,
                         cudaFuncAttributeMaxDynamicSharedMemorySize, DYN);

    // 0. all weight transposes (tf32 pre-rounded) + bias concat, one launch
    transpose_all_kernel<<<738, dim3(32, 8)>>>(W_val, W_off, W_attn, W_out,
                                               W_f1, W_f2, b_off, b_attn);

    // 1. q = src + pos
    int n4 = M_TOK * DIM / 4;
    add4_kernel<<<(n4 + 255) / 256, 256>>>((const float4*)src, (const float4*)pos,
                                           (float4*)q, n4);

    dim3 grid256(DIM / 128, M_TOK / 128);   // (2, 340)
    dim3 gridOA(384 / 128, M_TOK / 128);    // (3, 340)
    dim3 gridFFN(DFF / 128, M_TOK / 128);   // (8, 340)

    // 2. value = fp16(src @ W_val + b_val)
    gemm_tc_kernel<<<grid256, 256, DYN>>>(src, wtv, b_val, nullptr, (float*)val,
                                          M_TOK, DIM, DIM, 3);
    // 3. [off | attn logits] = q @ [W_off | W_attn] + [b_off | b_attn]
    gemm_tc_kernel<<<gridOA, 256, DYN>>>(q, wtoa, boa, nullptr, oa,
                                         M_TOK, 384, DIM, 0);
    // 4. deformable sampling (softmax fused) -> acc
    deform_sample_kernel<<<M_TOK * NHEAD / 8, 256>>>(val, oa, refp, acc);

    // 5. y = acc @ W_out + b_out + src
    gemm_tc_kernel<<<grid256, 256, DYN>>>(acc, wtu, b_out, src, y,
                                          M_TOK, DIM, DIM, 2);
    // 6. x = LN1(y)
    ln_kernel<<<M_TOK / 8, 256>>>(y, ln1g, ln1b, x, M_TOK);

    // 7. ffn = relu(x @ W_f1 + b_f1)
    gemm_tc_kernel<<<gridFFN, 256, DYN>>>(x, wt1, b_f1, nullptr, ffn,
                                          M_TOK, DFF, DIM, 1);
    // 8. y2 = ffn @ W_f2 + b_f2 + x
    gemm_tc_kernel<<<grid256, 256, DYN>>>(ffn, wt2, b_f2, x, y2,
                                          M_TOK, DIM, DFF, 2);
    // 9. out = LN2(y2)
    ln_kernel<<<M_TOK / 8, 256>>>(y2, ln2g, ln2b, out, M_TOK);
}

// round 12
// speedup vs baseline: 1.0702x; 1.0702x over previous
#include <cuda_runtime.h>
#include <cuda_fp16.h>
#include <stdint.h>
#include <math.h>

// Problem constants (fixed by setup_inputs)
#define BATCH 2
#define S_TOT 21760
#define DIM 256
#define NHEAD 8
#define NLVL 4
#define NPT 4
#define DFF 1024
#define DHEAD 32
#define M_TOK (BATCH * S_TOT)   // 43520 rows

// ---------------------------------------------------------------------------
// Scratch (device globals — no runtime allocation allowed)
// ---------------------------------------------------------------------------
__device__ float g_q     [M_TOK * DIM];
__device__ __half g_val  [M_TOK * DIM];   // fp16 value tensor
__device__ float g_oa    [M_TOK * 384];   // merged offsets(256) + attn logits(128)
__device__ float g_acc   [M_TOK * DIM];
__device__ float g_y     [M_TOK * DIM];
__device__ float g_x     [M_TOK * DIM];
__device__ float g_ffn   [M_TOK * DFF];
__device__ float g_y2    [M_TOK * DIM];

// Transposed (K-major), tf32-pre-rounded weights: WT[n*K + k] = tf32(W[k*N + n])
__device__ float g_WT_val [DIM * DIM];
__device__ float g_WT_oa  [384 * DIM];
__device__ float g_WT_out [DIM * DIM];
__device__ float g_WT_f1  [DFF * DIM];
__device__ float g_WT_f2  [DIM * DFF];
__device__ float g_b_oa   [384];

__device__ __forceinline__ uint32_t f2tf32(float f) {
    uint32_t u;
    asm("cvt.rna.tf32.f32 %0, %1;" : "=r"(u) : "f"(f));
    return u;
}

__device__ __forceinline__ uint32_t smem_u32(const void* p) {
    uint32_t a;
    asm("{ .reg .u64 t; cvta.to.shared.u64 t, %1; cvt.u32.u64 %0, t; }"
        : "=r"(a) : "l"(p));
    return a;
}

// ---------------------------------------------------------------------------
// One launch: all weight transposes (with tf32 pre-round) + bias concat.
// ---------------------------------------------------------------------------
__global__ void transpose_all_kernel(
    const float* __restrict__ W_val, const float* __restrict__ W_off,
    const float* __restrict__ W_attn, const float* __restrict__ W_out,
    const float* __restrict__ W_f1,  const float* __restrict__ W_f2,
    const float* __restrict__ b_off, const float* __restrict__ b_attn)
{
    const int bid = blockIdx.x;
    const int tx = threadIdx.x, ty0 = threadIdx.y;

    if (bid >= 736) {   // bias concat blocks (736, 737)
        int idx = (bid - 736) * 256 + ty0 * 32 + tx;
        if (idx < 384)
            g_b_oa[idx] = (idx < 256) ? b_off[idx] : b_attn[idx - 256];
        return;
    }

    const float* W; float* WT; int K, N, lt;
    if      (bid < 64)  { W = W_val;  WT = g_WT_val;            K = 256;  N = 256;  lt = bid; }
    else if (bid < 128) { W = W_off;  WT = g_WT_oa;             K = 256;  N = 256;  lt = bid - 64; }
    else if (bid < 160) { W = W_attn; WT = g_WT_oa + 256 * 256; K = 256;  N = 128;  lt = bid - 128; }
    else if (bid < 224) { W = W_out;  WT = g_WT_out;            K = 256;  N = 256;  lt = bid - 160; }
    else if (bid < 480) { W = W_f1;   WT = g_WT_f1;             K = 256;  N = 1024; lt = bid - 224; }
    else                { W = W_f2;   WT = g_WT_f2;             K = 1024; N = 256;  lt = bid - 480; }

    const int tiles_x = N >> 5;
    const int bn = (lt % tiles_x) * 32;
    const int bk = (lt / tiles_x) * 32;

    __shared__ float tile[32][33];
#pragma unroll
    for (int i = 0; i < 4; i++) {
        int ty = ty0 + i * 8;
        tile[ty][tx] = W[(size_t)(bk + ty) * N + bn + tx];
    }
    __syncthreads();
#pragma unroll
    for (int i = 0; i < 4; i++) {
        int ty = ty0 + i * 8;
        WT[(size_t)(bn + ty) * K + bk + tx] =
            __uint_as_float(f2tf32(tile[tx][ty]));
    }
}

// ---------------------------------------------------------------------------
// tf32 mma.sync GEMM, cp.async 4-stage pipeline, one barrier per chunk.
// C[M,N] = A[M,K] @ WT[N,K]^T + bias (+relu / +res / fp16-out)
// BM=BN=128, BK=16, 128 threads (4 warps, 2x2), warp tile 64x64.
// Smem traffic: each tile byte re-read by only 2 warps (was 4 for A).
// A implicitly truncated to tf32 by HMMA (RZ); WT pre-rounded RNA.
// fuse: 0 none, 1 relu, 2 residual add, 3 write fp16
// ---------------------------------------------------------------------------
#define BKC 16
#define SMS 20   // smem row stride (floats): conflict-free for frag patterns
#define STG 4
#define BUF (128 * SMS)

__global__ __launch_bounds__(128, 2) void gemm_tc_kernel(
    const float* __restrict__ A, const float* __restrict__ WT,
    const float* __restrict__ bias, const float* __restrict__ res,
    float* __restrict__ C, int M, int N, int K, int fuse)
{
    extern __shared__ float smem[];
    float* sA = smem;               // STG * BUF floats
    float* sB = smem + STG * BUF;   // STG * BUF floats

    const int t    = threadIdx.x;   // 0..127
    const int wid  = t >> 5;        // 0..3
    const int lane = t & 31;
    const int wm   = (wid >> 1) * 64;   // 0 or 64
    const int wn   = (wid & 1) * 64;    // 0 or 64
    const int bm   = blockIdx.y * 128;
    const int bn   = blockIdx.x * 128;

    // copy units: 512 x 16B per operand tile; thread t does units t+128*i
    const int r0 = t >> 2,           s0 = (t & 3) << 2;
    const int r1 = (t + 128) >> 2,   s1 = ((t + 128) & 3) << 2;
    const int r2 = (t + 256) >> 2,   s2 = ((t + 256) & 3) << 2;
    const int r3 = (t + 384) >> 2,   s3 = ((t + 384) & 3) << 2;

    const float* Ab = A  + (size_t)bm * K;
    const float* Bb = WT + (size_t)bn * K;

    float acc[4][8][4];
#pragma unroll
    for (int i = 0; i < 4; i++)
#pragma unroll
        for (int j = 0; j < 8; j++)
#pragma unroll
            for (int e = 0; e < 4; e++) acc[i][j][e] = 0.f;

    const int nch = K >> 4;

    auto issue = [&](int c) {
        const int s = c % STG;
        float* a = sA + s * BUF;
        float* b = sB + s * BUF;
        const int kb = c << 4;
        uint32_t d;
        d = smem_u32(a + r0 * SMS + s0);
        asm volatile("cp.async.ca.shared.global [%0], [%1], 16;"
                     :: "r"(d), "l"(Ab + (size_t)r0 * K + kb + s0) : "memory");
        d = smem_u32(a + r1 * SMS + s1);
        asm volatile("cp.async.ca.shared.global [%0], [%1], 16;"
                     :: "r"(d), "l"(Ab + (size_t)r1 * K + kb + s1) : "memory");
        d = smem_u32(a + r2 * SMS + s2);
        asm volatile("cp.async.ca.shared.global [%0], [%1], 16;"
                     :: "r"(d), "l"(Ab + (size_t)r2 * K + kb + s2) : "memory");
        d = smem_u32(a + r3 * SMS + s3);
        asm volatile("cp.async.ca.shared.global [%0], [%1], 16;"
                     :: "r"(d), "l"(Ab + (size_t)r3 * K + kb + s3) : "memory");
        d = smem_u32(b + r0 * SMS + s0);
        asm volatile("cp.async.ca.shared.global [%0], [%1], 16;"
                     :: "r"(d), "l"(Bb + (size_t)r0 * K + kb + s0) : "memory");
        d = smem_u32(b + r1 * SMS + s1);
        asm volatile("cp.async.ca.shared.global [%0], [%1], 16;"
                     :: "r"(d), "l"(Bb + (size_t)r1 * K + kb + s1) : "memory");
        d = smem_u32(b + r2 * SMS + s2);
        asm volatile("cp.async.ca.shared.global [%0], [%1], 16;"
                     :: "r"(d), "l"(Bb + (size_t)r2 * K + kb + s2) : "memory");
        d = smem_u32(b + r3 * SMS + s3);
        asm volatile("cp.async.ca.shared.global [%0], [%1], 16;"
                     :: "r"(d), "l"(Bb + (size_t)r3 * K + kb + s3) : "memory");
        asm volatile("cp.async.commit_group;" ::: "memory");
    };

    const int lr = lane >> 2;   // 0..7
    const int lk = lane & 3;    // 0..3

    auto compute = [&](int c) {
        const int s = c % STG;
        const float* a  = sA + s * BUF;
        const float* bp = sB + s * BUF;
#pragma unroll
        for (int ks = 0; ks < BKC; ks += 8) {
            uint32_t af[4][4], bf[8][2];
#pragma unroll
            for (int mt = 0; mt < 4; mt++) {
                int mr = wm + mt * 16 + lr;
                af[mt][0] = __float_as_uint(a[mr * SMS + ks + lk]);
                af[mt][1] = __float_as_uint(a[(mr + 8) * SMS + ks + lk]);
                af[mt][2] = __float_as_uint(a[mr * SMS + ks + lk + 4]);
                af[mt][3] = __float_as_uint(a[(mr + 8) * SMS + ks + lk + 4]);
            }
#pragma unroll
            for (int nt = 0; nt < 8; nt++) {
                int nc = wn + nt * 8 + lr;
                bf[nt][0] = __float_as_uint(bp[nc * SMS + ks + lk]);
                bf[nt][1] = __float_as_uint(bp[nc * SMS + ks + lk + 4]);
            }
#pragma unroll
            for (int mt = 0; mt < 4; mt++)
#pragma unroll
                for (int nt = 0; nt < 8; nt++) {
                    asm volatile(
                        "mma.sync.aligned.m16n8k8.row.col.f32.tf32.tf32.f32 "
                        "{%0,%1,%2,%3}, {%4,%5,%6,%7}, {%8,%9}, {%0,%1,%2,%3};"
                        : "+f"(acc[mt][nt][0]), "+f"(acc[mt][nt][1]),
                          "+f"(acc[mt][nt][2]), "+f"(acc[mt][nt][3])
                        : "r"(af[mt][0]), "r"(af[mt][1]),
                          "r"(af[mt][2]), "r"(af[mt][3]),
                          "r"(bf[nt][0]), "r"(bf[nt][1]));
                }
        }
    };

    issue(0);
    if (nch > 1) issue(1);
    if (nch > 2) issue(2);

    for (int c = 0; c < nch; c++) {
        asm volatile("cp.async.wait_group 2;" ::: "memory");
        __syncthreads();
        if (c + 3 < nch) issue(c + 3);
        compute(c);
    }

    // ---- epilogue ----
    const int cL = (lane & 3) * 2;
#pragma unroll
    for (int mt = 0; mt < 4; mt++) {
        int row = bm + wm + mt * 16 + lr;
#pragma unroll
        for (int nt = 0; nt < 8; nt++) {
            int col = bn + wn + nt * 8 + cL;
            float2 v0, v1;
            v0.x = acc[mt][nt][0] + bias[col];
            v0.y = acc[mt][nt][1] + bias[col + 1];
            v1.x = acc[mt][nt][2] + bias[col];
            v1.y = acc[mt][nt][3] + bias[col + 1];
            if (fuse == 1) {
                v0.x = fmaxf(v0.x, 0.f); v0.y = fmaxf(v0.y, 0.f);
                v1.x = fmaxf(v1.x, 0.f); v1.y = fmaxf(v1.y, 0.f);
            } else if (fuse == 2) {
                float2 r0v = *(const float2*)&res[(size_t)row * N + col];
                float2 r1v = *(const float2*)&res[(size_t)(row + 8) * N + col];
                v0.x += r0v.x; v0.y += r0v.y;
                v1.x += r1v.x; v1.y += r1v.y;
            }
            if (fuse == 3) {
                __half* Ch = (__half*)C;
                *(__half2*)&Ch[(size_t)row * N + col] =
                    __floats2half2_rn(v0.x, v0.y);
                *(__half2*)&Ch[(size_t)(row + 8) * N + col] =
                    __floats2half2_rn(v1.x, v1.y);
            } else {
                *(float2*)&C[(size_t)row * N + col] = v0;
                *(float2*)&C[(size_t)(row + 8) * N + col] = v1;
            }
        }
    }
}

// ---------------------------------------------------------------------------
// q = src + pos
// ---------------------------------------------------------------------------
__global__ void add4_kernel(const float4* __restrict__ a,
                            const float4* __restrict__ b,
                            float4* __restrict__ c, int n4) {
    int i = blockIdx.x * blockDim.x + threadIdx.x;
    if (i < n4) {
        float4 x = a[i], y = b[i];
        x.x += y.x; x.y += y.y; x.z += y.z; x.w += y.w;
        c[i] = x;
    }
}

// ---------------------------------------------------------------------------
// Deformable sampling with FUSED softmax, fp16 value tensor.
// One warp per (token, head); lane = channel (DH=32).
// ---------------------------------------------------------------------------
__global__ __launch_bounds__(256) void deform_sample_kernel(
    const __half* __restrict__ value, const float* __restrict__ oa,
    const float* __restrict__ refp, float* __restrict__ out)
{
    const int lane = threadIdx.x & 31;
    const int wid  = blockIdx.x * (blockDim.x >> 5) + (threadIdx.x >> 5);
    const int tok = wid >> 3;
    const int h   = wid & 7;
    const int b   = tok / S_TOT;

    float offv  = oa[(size_t)tok * 384 + h * 32 + lane];
    float logit = (lane < 16) ? oa[(size_t)tok * 384 + 256 + h * 16 + lane] : -1e30f;
    float refv  = (lane < 8)  ? refp[(size_t)tok * 8 + lane] : 0.f;

    // softmax over 16 logits held in lanes 0..15
    float m = logit;
#pragma unroll
    for (int o = 8; o > 0; o >>= 1) m = fmaxf(m, __shfl_xor_sync(0xffffffffu, m, o));
    float e = (lane < 16) ? expf(logit - m) : 0.f;
    float ssum = e;
#pragma unroll
    for (int o = 8; o > 0; o >>= 1) ssum += __shfl_xor_sync(0xffffffffu, ssum, o);
    float attnv = e / ssum;

    const __half* vbase = value + (size_t)b * S_TOT * 256 + h * 32 + lane;

    const int HW[4]     = {128, 64, 32, 16};
    const int starts[4] = {0, 16384, 20480, 21504};

    float acc = 0.f;
#pragma unroll
    for (int l = 0; l < 4; l++) {
        const int   Hl = HW[l], Wl = HW[l];
        const float fH = (float)Hl, fW = (float)Wl;
        float rx = __shfl_sync(0xffffffffu, refv, 2 * l);
        float ry = __shfl_sync(0xffffffffu, refv, 2 * l + 1);
        const __half* vlev = vbase + (size_t)starts[l] * 256;
#pragma unroll
        for (int p = 0; p < 4; p++) {
            int j = l * 4 + p;
            float ox = __shfl_sync(0xffffffffu, offv, 2 * j);
            float oy = __shfl_sync(0xffffffffu, offv, 2 * j + 1);
            float aw = __shfl_sync(0xffffffffu, attnv, j);

            float locx = rx + ox / fW;
            float locy = ry + oy / fH;
            float x = locx * fW - 0.5f;
            float y = locy * fH - 0.5f;
            float x0f = floorf(x), y0f = floorf(y);
            float wx = x - x0f, wy = y - y0f;
            int x0 = (int)x0f, y0 = (int)y0f;

            bool vx0 = (x0 >= 0) && (x0 < Wl);
            bool vx1 = (x0 + 1 >= 0) && (x0 + 1 < Wl);
            bool vy0 = (y0 >= 0) && (y0 < Hl);
            bool vy1 = (y0 + 1 >= 0) && (y0 + 1 < Hl);

            float samp = 0.f;
            if (vy0) {
                const __half* rowp = vlev + (size_t)(y0 * Wl) * 256;
                if (vx0) samp += (1.f - wx) * (1.f - wy) * __half2float(rowp[(size_t)x0 * 256]);
                if (vx1) samp += wx * (1.f - wy) * __half2float(rowp[(size_t)(x0 + 1) * 256]);
            }
            if (vy1) {
                const __half* rowp = vlev + (size_t)((y0 + 1) * Wl) * 256;
                if (vx0) samp += (1.f - wx) * wy * __half2float(rowp[(size_t)x0 * 256]);
                if (vx1) samp += wx * wy * __half2float(rowp[(size_t)(x0 + 1) * 256]);
            }
            acc += aw * samp;
        }
    }
    out[(size_t)tok * 256 + h * 32 + lane] = acc;
}

// ---------------------------------------------------------------------------
// LayerNorm over D=256: one warp per row.
// ---------------------------------------------------------------------------
__global__ __launch_bounds__(256) void ln_kernel(
    const float* __restrict__ in, const float* __restrict__ gamma,
    const float* __restrict__ beta, float* __restrict__ out, int rows)
{
    const int lane = threadIdx.x & 31;
    const int row  = blockIdx.x * 8 + (threadIdx.x >> 5);
    if (row >= rows) return;
    const float* p = in + (size_t)row * 256;

    float v[8];
    float s = 0.f;
#pragma unroll
    for (int i = 0; i < 8; i++) { v[i] = p[i * 32 + lane]; s += v[i]; }
#pragma unroll
    for (int o = 16; o > 0; o >>= 1) s += __shfl_xor_sync(0xffffffffu, s, o);
    float mu = s * (1.f / 256.f);

    float vs = 0.f;
#pragma unroll
    for (int i = 0; i < 8; i++) { float d = v[i] - mu; vs += d * d; }
#pragma unroll
    for (int o = 16; o > 0; o >>= 1) vs += __shfl_xor_sync(0xffffffffu, vs, o);
    float rstd = rsqrtf(vs * (1.f / 256.f) + 1e-5f);

    float* q = out + (size_t)row * 256;
#pragma unroll
    for (int i = 0; i < 8; i++) {
        int c = i * 32 + lane;
        q[c] = (v[i] - mu) * rstd * gamma[c] + beta[c];
    }
}

// ---------------------------------------------------------------------------
// Launch
// ---------------------------------------------------------------------------
extern "C" void kernel_launch(void* const* d_in, const int* in_sizes, int n_in,
                              void* d_out, int out_size) {
    const float* src    = (const float*)d_in[0];
    const float* pos    = (const float*)d_in[1];
    const float* refp   = (const float*)d_in[2];
    const float* W_off  = (const float*)d_in[5];
    const float* b_off  = (const float*)d_in[6];
    const float* W_attn = (const float*)d_in[7];
    const float* b_attn = (const float*)d_in[8];
    const float* W_val  = (const float*)d_in[9];
    const float* b_val  = (const float*)d_in[10];
    const float* W_out  = (const float*)d_in[11];
    const float* b_out  = (const float*)d_in[12];
    const float* W_f1   = (const float*)d_in[13];
    const float* b_f1   = (const float*)d_in[14];
    const float* W_f2   = (const float*)d_in[15];
    const float* b_f2   = (const float*)d_in[16];
    const float* ln1g   = (const float*)d_in[17];
    const float* ln1b   = (const float*)d_in[18];
    const float* ln2g   = (const float*)d_in[19];
    const float* ln2b   = (const float*)d_in[20];
    float* out = (float*)d_out;

    float *q, *oa, *acc, *y, *x, *ffn, *y2;
    __half* val;
    float *wtv, *wtoa, *wtu, *wt1, *wt2, *boa;
    cudaGetSymbolAddress((void**)&q,    g_q);
    cudaGetSymbolAddress((void**)&val,  g_val);
    cudaGetSymbolAddress((void**)&oa,   g_oa);
    cudaGetSymbolAddress((void**)&acc,  g_acc);
    cudaGetSymbolAddress((void**)&y,    g_y);
    cudaGetSymbolAddress((void**)&x,    g_x);
    cudaGetSymbolAddress((void**)&ffn,  g_ffn);
    cudaGetSymbolAddress((void**)&y2,   g_y2);
    cudaGetSymbolAddress((void**)&wtv,  g_WT_val);
    cudaGetSymbolAddress((void**)&wtoa, g_WT_oa);
    cudaGetSymbolAddress((void**)&wtu,  g_WT_out);
    cudaGetSymbolAddress((void**)&wt1,  g_WT_f1);
    cudaGetSymbolAddress((void**)&wt2,  g_WT_f2);
    cudaGetSymbolAddress((void**)&boa,  g_b_oa);

    const int DYN = STG * BUF * 2 * 4;   // 81920 B
    cudaFuncSetAttribute(gemm_tc_kernel,
                         cudaFuncAttributeMaxDynamicSharedMemorySize, DYN);

    // 0. all weight transposes (tf32 pre-rounded) + bias concat, one launch
    transpose_all_kernel<<<738, dim3(32, 8)>>>(W_val, W_off, W_attn, W_out,
                                               W_f1, W_f2, b_off, b_attn);

    // 1. q = src + pos
    int n4 = M_TOK * DIM / 4;
    add4_kernel<<<(n4 + 255) / 256, 256>>>((const float4*)src, (const float4*)pos,
                                           (float4*)q, n4);

    dim3 grid256(DIM / 128, M_TOK / 128);   // (2, 340)
    dim3 gridOA(384 / 128, M_TOK / 128);    // (3, 340)
    dim3 gridFFN(DFF / 128, M_TOK / 128);   // (8, 340)

    // 2. value = fp16(src @ W_val + b_val)
    gemm_tc_kernel<<<grid256, 128, DYN>>>(src, wtv, b_val, nullptr, (float*)val,
                                          M_TOK, DIM, DIM, 3);
    // 3. [off | attn logits] = q @ [W_off | W_attn] + [b_off | b_attn]
    gemm_tc_kernel<<<gridOA, 128, DYN>>>(q, wtoa, boa, nullptr, oa,
                                         M_TOK, 384, DIM, 0);
    // 4. deformable sampling (softmax fused) -> acc
    deform_sample_kernel<<<M_TOK * NHEAD / 8, 256>>>(val, oa, refp, acc);

    // 5. y = acc @ W_out + b_out + src
    gemm_tc_kernel<<<grid256, 128, DYN>>>(acc, wtu, b_out, src, y,
                                          M_TOK, DIM, DIM, 2);
    // 6. x = LN1(y)
    ln_kernel<<<M_TOK / 8, 256>>>(y, ln1g, ln1b, x, M_TOK);

    // 7. ffn = relu(x @ W_f1 + b_f1)
    gemm_tc_kernel<<<gridFFN, 128, DYN>>>(x, wt1, b_f1, nullptr, ffn,
                                          M_TOK, DFF, DIM, 1);
    // 8. y2 = ffn @ W_f2 + b_f2 + x
    gemm_tc_kernel<<<grid256, 128, DYN>>>(ffn, wt2, b_f2, x, y2,
                                          M_TOK, DIM, DFF, 2);
    // 9. out = LN2(y2)
    ln_kernel<<<M_TOK / 8, 256>>>(y2, ln2g, ln2b, out, M_TOK);
}

// round 14
// speedup vs baseline: 1.1198x; 1.0463x over previous
#include <cuda_runtime.h>
#include <cuda_fp16.h>
#include <stdint.h>
#include <math.h>

// Problem constants (fixed by setup_inputs)
#define BATCH 2
#define S_TOT 21760
#define DIM 256
#define NHEAD 8
#define NLVL 4
#define NPT 4
#define DFF 1024
#define DHEAD 32
#define M_TOK (BATCH * S_TOT)   // 43520 rows

// ---------------------------------------------------------------------------
// Scratch (device globals — no runtime allocation allowed)
// ---------------------------------------------------------------------------
__device__ float g_q     [M_TOK * DIM];
__device__ __half g_val  [M_TOK * DIM];   // fp16 value tensor
__device__ float g_oa    [M_TOK * 384];   // merged offsets(256) + attn logits(128)
__device__ float g_acc   [M_TOK * DIM];
__device__ float g_y     [M_TOK * DIM];
__device__ float g_x     [M_TOK * DIM];
__device__ float g_ffn   [M_TOK * DFF];
__device__ float g_y2    [M_TOK * DIM];

// Transposed (K-major), tf32-pre-rounded weights: WT[n*K + k] = tf32(W[k*N + n])
__device__ float g_WT_val [DIM * DIM];
__device__ float g_WT_oa  [384 * DIM];
__device__ float g_WT_out [DIM * DIM];
__device__ float g_WT_f1  [DFF * DIM];
__device__ float g_WT_f2  [DIM * DFF];
__device__ float g_b_oa   [384];

__device__ __forceinline__ uint32_t f2tf32(float f) {
    uint32_t u;
    asm("cvt.rna.tf32.f32 %0, %1;" : "=r"(u) : "f"(f));
    return u;
}

__device__ __forceinline__ uint32_t smem_u32(const void* p) {
    uint32_t a;
    asm("{ .reg .u64 t; cvta.to.shared.u64 t, %1; cvt.u32.u64 %0, t; }"
        : "=r"(a) : "l"(p));
    return a;
}

// ---------------------------------------------------------------------------
// One launch: all weight transposes (with tf32 pre-round) + bias concat.
// ---------------------------------------------------------------------------
__global__ void transpose_all_kernel(
    const float* __restrict__ W_val, const float* __restrict__ W_off,
    const float* __restrict__ W_attn, const float* __restrict__ W_out,
    const float* __restrict__ W_f1,  const float* __restrict__ W_f2,
    const float* __restrict__ b_off, const float* __restrict__ b_attn)
{
    const int bid = blockIdx.x;
    const int tx = threadIdx.x, ty0 = threadIdx.y;

    if (bid >= 736) {   // bias concat blocks (736, 737)
        int idx = (bid - 736) * 256 + ty0 * 32 + tx;
        if (idx < 384)
            g_b_oa[idx] = (idx < 256) ? b_off[idx] : b_attn[idx - 256];
        return;
    }

    const float* W; float* WT; int K, N, lt;
    if      (bid < 64)  { W = W_val;  WT = g_WT_val;            K = 256;  N = 256;  lt = bid; }
    else if (bid < 128) { W = W_off;  WT = g_WT_oa;             K = 256;  N = 256;  lt = bid - 64; }
    else if (bid < 160) { W = W_attn; WT = g_WT_oa + 256 * 256; K = 256;  N = 128;  lt = bid - 128; }
    else if (bid < 224) { W = W_out;  WT = g_WT_out;            K = 256;  N = 256;  lt = bid - 160; }
    else if (bid < 480) { W = W_f1;   WT = g_WT_f1;             K = 256;  N = 1024; lt = bid - 224; }
    else                { W = W_f2;   WT = g_WT_f2;             K = 1024; N = 256;  lt = bid - 480; }

    const int tiles_x = N >> 5;
    const int bn = (lt % tiles_x) * 32;
    const int bk = (lt / tiles_x) * 32;

    __shared__ float tile[32][33];
#pragma unroll
    for (int i = 0; i < 4; i++) {
        int ty = ty0 + i * 8;
        tile[ty][tx] = W[(size_t)(bk + ty) * N + bn + tx];
    }
    __syncthreads();
#pragma unroll
    for (int i = 0; i < 4; i++) {
        int ty = ty0 + i * 8;
        WT[(size_t)(bn + ty) * K + bk + tx] =
            __uint_as_float(f2tf32(tile[tx][ty]));
    }
}

// ---------------------------------------------------------------------------
// tf32 mma.sync GEMM, cp.async 4-stage pipeline, one barrier per chunk.
// C[M,N] = A[M,K] @ WT[N,K]^T + bias (+relu / +res / fp16-out)
// BM=BN=128, BK=16, 128 threads (4 warps, 2x2), warp tile 64x64.
// fuse: 0 none, 1 relu, 2 residual add, 3 write fp16
// ---------------------------------------------------------------------------
#define BKC 16
#define SMS 20   // smem row stride (floats): conflict-free for frag patterns
#define STG 4
#define BUF (128 * SMS)

__global__ __launch_bounds__(128, 2) void gemm_tc_kernel(
    const float* __restrict__ A, const float* __restrict__ WT,
    const float* __restrict__ bias, const float* __restrict__ res,
    float* __restrict__ C, int M, int N, int K, int fuse)
{
    extern __shared__ float smem[];
    float* sA = smem;               // STG * BUF floats
    float* sB = smem + STG * BUF;   // STG * BUF floats

    const int t    = threadIdx.x;   // 0..127
    const int wid  = t >> 5;        // 0..3
    const int lane = t & 31;
    const int wm   = (wid >> 1) * 64;   // 0 or 64
    const int wn   = (wid & 1) * 64;    // 0 or 64
    const int bm   = blockIdx.y * 128;
    const int bn   = blockIdx.x * 128;

    // copy units: 512 x 16B per operand tile; thread t does units t+128*i
    const int r0 = t >> 2,           s0 = (t & 3) << 2;
    const int r1 = (t + 128) >> 2,   s1 = ((t + 128) & 3) << 2;
    const int r2 = (t + 256) >> 2,   s2 = ((t + 256) & 3) << 2;
    const int r3 = (t + 384) >> 2,   s3 = ((t + 384) & 3) << 2;

    const float* Ab = A  + (size_t)bm * K;
    const float* Bb = WT + (size_t)bn * K;

    float acc[4][8][4];
#pragma unroll
    for (int i = 0; i < 4; i++)
#pragma unroll
        for (int j = 0; j < 8; j++)
#pragma unroll
            for (int e = 0; e < 4; e++) acc[i][j][e] = 0.f;

    const int nch = K >> 4;

    auto issue = [&](int c) {
        const int s = c % STG;
        float* a = sA + s * BUF;
        float* b = sB + s * BUF;
        const int kb = c << 4;
        uint32_t d;
        d = smem_u32(a + r0 * SMS + s0);
        asm volatile("cp.async.ca.shared.global [%0], [%1], 16;"
                     :: "r"(d), "l"(Ab + (size_t)r0 * K + kb + s0) : "memory");
        d = smem_u32(a + r1 * SMS + s1);
        asm volatile("cp.async.ca.shared.global [%0], [%1], 16;"
                     :: "r"(d), "l"(Ab + (size_t)r1 * K + kb + s1) : "memory");
        d = smem_u32(a + r2 * SMS + s2);
        asm volatile("cp.async.ca.shared.global [%0], [%1], 16;"
                     :: "r"(d), "l"(Ab + (size_t)r2 * K + kb + s2) : "memory");
        d = smem_u32(a + r3 * SMS + s3);
        asm volatile("cp.async.ca.shared.global [%0], [%1], 16;"
                     :: "r"(d), "l"(Ab + (size_t)r3 * K + kb + s3) : "memory");
        d = smem_u32(b + r0 * SMS + s0);
        asm volatile("cp.async.ca.shared.global [%0], [%1], 16;"
                     :: "r"(d), "l"(Bb + (size_t)r0 * K + kb + s0) : "memory");
        d = smem_u32(b + r1 * SMS + s1);
        asm volatile("cp.async.ca.shared.global [%0], [%1], 16;"
                     :: "r"(d), "l"(Bb + (size_t)r1 * K + kb + s1) : "memory");
        d = smem_u32(b + r2 * SMS + s2);
        asm volatile("cp.async.ca.shared.global [%0], [%1], 16;"
                     :: "r"(d), "l"(Bb + (size_t)r2 * K + kb + s2) : "memory");
        d = smem_u32(b + r3 * SMS + s3);
        asm volatile("cp.async.ca.shared.global [%0], [%1], 16;"
                     :: "r"(d), "l"(Bb + (size_t)r3 * K + kb + s3) : "memory");
        asm volatile("cp.async.commit_group;" ::: "memory");
    };

    const int lr = lane >> 2;   // 0..7
    const int lk = lane & 3;    // 0..3

    auto compute = [&](int c) {
        const int s = c % STG;
        const float* a  = sA + s * BUF;
        const float* bp = sB + s * BUF;
#pragma unroll
        for (int ks = 0; ks < BKC; ks += 8) {
            uint32_t af[4][4], bf[8][2];
#pragma unroll
            for (int mt = 0; mt < 4; mt++) {
                int mr = wm + mt * 16 + lr;
                af[mt][0] = __float_as_uint(a[mr * SMS + ks + lk]);
                af[mt][1] = __float_as_uint(a[(mr + 8) * SMS + ks + lk]);
                af[mt][2] = __float_as_uint(a[mr * SMS + ks + lk + 4]);
                af[mt][3] = __float_as_uint(a[(mr + 8) * SMS + ks + lk + 4]);
            }
#pragma unroll
            for (int nt = 0; nt < 8; nt++) {
                int nc = wn + nt * 8 + lr;
                bf[nt][0] = __float_as_uint(bp[nc * SMS + ks + lk]);
                bf[nt][1] = __float_as_uint(bp[nc * SMS + ks + lk + 4]);
            }
#pragma unroll
            for (int mt = 0; mt < 4; mt++)
#pragma unroll
                for (int nt = 0; nt < 8; nt++) {
                    asm volatile(
                        "mma.sync.aligned.m16n8k8.row.col.f32.tf32.tf32.f32 "
                        "{%0,%1,%2,%3}, {%4,%5,%6,%7}, {%8,%9}, {%0,%1,%2,%3};"
                        : "+f"(acc[mt][nt][0]), "+f"(acc[mt][nt][1]),
                          "+f"(acc[mt][nt][2]), "+f"(acc[mt][nt][3])
                        : "r"(af[mt][0]), "r"(af[mt][1]),
                          "r"(af[mt][2]), "r"(af[mt][3]),
                          "r"(bf[nt][0]), "r"(bf[nt][1]));
                }
        }
    };

    issue(0);
    if (nch > 1) issue(1);
    if (nch > 2) issue(2);

    for (int c = 0; c < nch; c++) {
        asm volatile("cp.async.wait_group 2;" ::: "memory");
        __syncthreads();
        if (c + 3 < nch) issue(c + 3);
        compute(c);
    }

    // ---- epilogue ----
    const int cL = (lane & 3) * 2;
#pragma unroll
    for (int mt = 0; mt < 4; mt++) {
        int row = bm + wm + mt * 16 + lr;
#pragma unroll
        for (int nt = 0; nt < 8; nt++) {
            int col = bn + wn + nt * 8 + cL;
            float2 v0, v1;
            v0.x = acc[mt][nt][0] + bias[col];
            v0.y = acc[mt][nt][1] + bias[col + 1];
            v1.x = acc[mt][nt][2] + bias[col];
            v1.y = acc[mt][nt][3] + bias[col + 1];
            if (fuse == 1) {
                v0.x = fmaxf(v0.x, 0.f); v0.y = fmaxf(v0.y, 0.f);
                v1.x = fmaxf(v1.x, 0.f); v1.y = fmaxf(v1.y, 0.f);
            } else if (fuse == 2) {
                float2 r0v = *(const float2*)&res[(size_t)row * N + col];
                float2 r1v = *(const float2*)&res[(size_t)(row + 8) * N + col];
                v0.x += r0v.x; v0.y += r0v.y;
                v1.x += r1v.x; v1.y += r1v.y;
            }
            if (fuse == 3) {
                __half* Ch = (__half*)C;
                *(__half2*)&Ch[(size_t)row * N + col] =
                    __floats2half2_rn(v0.x, v0.y);
                *(__half2*)&Ch[(size_t)(row + 8) * N + col] =
                    __floats2half2_rn(v1.x, v1.y);
            } else {
                *(float2*)&C[(size_t)row * N + col] = v0;
                *(float2*)&C[(size_t)(row + 8) * N + col] = v1;
            }
        }
    }
}

// ---------------------------------------------------------------------------
// q = src + pos
// ---------------------------------------------------------------------------
__global__ void add4_kernel(const float4* __restrict__ a,
                            const float4* __restrict__ b,
                            float4* __restrict__ c, int n4) {
    int i = blockIdx.x * blockDim.x + threadIdx.x;
    if (i < n4) {
        float4 x = a[i], y = b[i];
        x.x += y.x; x.y += y.y; x.z += y.z; x.w += y.w;
        c[i] = x;
    }
}

// ---------------------------------------------------------------------------
// Deformable sampling, half-warp parallel, __half2 gathers, fused softmax.
// One warp per (token, head). Lane = half2 channel pair (16 lanes = 32 ch).
// Half-warp 0 processes samples 0..7 (levels 0,1), half-warp 1 samples 8..15
// (levels 2,3). Level of sample j = j>>2 = hw*2 + (s>>2).
// ---------------------------------------------------------------------------
__global__ __launch_bounds__(256) void deform_sample_kernel(
    const __half* __restrict__ value, const float* __restrict__ oa,
    const float* __restrict__ refp, float* __restrict__ out)
{
    const int lane = threadIdx.x & 31;
    const int wid  = blockIdx.x * 8 + (threadIdx.x >> 5);
    const int tok = wid >> 3;
    const int h   = wid & 7;
    const int b   = tok / S_TOT;
    const int hw  = lane >> 4;    // half-warp id
    const int ch  = lane & 15;    // half2 channel index

    float offv  = oa[(size_t)tok * 384 + h * 32 + lane];
    float logit = (lane < 16) ? oa[(size_t)tok * 384 + 256 + h * 16 + lane] : -1e30f;
    float refv  = (lane < 8)  ? refp[(size_t)tok * 8 + lane] : 0.f;

    // softmax over 16 logits held in lanes 0..15
    float m = logit;
#pragma unroll
    for (int o = 8; o > 0; o >>= 1) m = fmaxf(m, __shfl_xor_sync(0xffffffffu, m, o));
    float e = (lane < 16) ? expf(logit - m) : 0.f;
    float ssum = e;
#pragma unroll
    for (int o = 8; o > 0; o >>= 1) ssum += __shfl_xor_sync(0xffffffffu, ssum, o);
    float attnv = e / ssum;

    // base pointer for this (batch, head, channel-pair), in half2 units
    const __half2* vb =
        (const __half2*)(value + (size_t)b * S_TOT * 256 + h * 32) + ch;

    float accx = 0.f, accy = 0.f;
#pragma unroll
    for (int s = 0; s < 8; s++) {
        const int ls = s >> 2;            // compile-time 0/1
        const int l  = hw * 2 + ls;       // per-lane level
        const int j  = hw * 8 + s;        // per-lane sample index
        const int Wl = 128 >> l;
        const float fW = (float)Wl;
        // level start (tokens): hw selects between {0,16384} and {20480,21504}
        const int start = hw ? (ls ? 21504 : 20480) : (ls ? 16384 : 0);

        float rx = __shfl_sync(0xffffffffu, refv, 2 * l);
        float ry = __shfl_sync(0xffffffffu, refv, 2 * l + 1);
        float ox = __shfl_sync(0xffffffffu, offv, 2 * j);
        float oy = __shfl_sync(0xffffffffu, offv, 2 * j + 1);
        float aw = __shfl_sync(0xffffffffu, attnv, j);

        float locx = rx + ox / fW;
        float locy = ry + oy / fW;
        float x = locx * fW - 0.5f;
        float y = locy * fW - 0.5f;
        float x0f = floorf(x), y0f = floorf(y);
        float wx = x - x0f, wy = y - y0f;
        int x0 = (int)x0f, y0 = (int)y0f;
        int x1 = x0 + 1,   y1 = y0 + 1;

        bool vx0 = (x0 >= 0) && (x0 < Wl);
        bool vx1 = (x1 >= 0) && (x1 < Wl);
        bool vy0 = (y0 >= 0) && (y0 < Wl);
        bool vy1 = (y1 >= 0) && (y1 < Wl);

        int x0c = min(max(x0, 0), Wl - 1);
        int x1c = min(max(x1, 0), Wl - 1);
        int y0c = min(max(y0, 0), Wl - 1);
        int y1c = min(max(y1, 0), Wl - 1);

        float w00 = (vx0 && vy0) ? (1.f - wx) * (1.f - wy) * aw : 0.f;
        float w01 = (vx1 && vy0) ? wx * (1.f - wy) * aw : 0.f;
        float w10 = (vx0 && vy1) ? (1.f - wx) * wy * aw : 0.f;
        float w11 = (vx1 && vy1) ? wx * wy * aw : 0.f;

        const __half2* vl = vb + (size_t)start * 128;   // 128 half2 per token
        float2 f00 = __half22float2(vl[(size_t)(y0c * Wl + x0c) * 128]);
        float2 f01 = __half22float2(vl[(size_t)(y0c * Wl + x1c) * 128]);
        float2 f10 = __half22float2(vl[(size_t)(y1c * Wl + x0c) * 128]);
        float2 f11 = __half22float2(vl[(size_t)(y1c * Wl + x1c) * 128]);

        accx += w00 * f00.x + w01 * f01.x + w10 * f10.x + w11 * f11.x;
        accy += w00 * f00.y + w01 * f01.y + w10 * f10.y + w11 * f11.y;
    }

    // combine the two half-warps (same channels, disjoint samples)
    accx += __shfl_xor_sync(0xffffffffu, accx, 16);
    accy += __shfl_xor_sync(0xffffffffu, accy, 16);

    if (lane < 16) {
        float2 v; v.x = accx; v.y = accy;
        *(float2*)&out[(size_t)tok * 256 + h * 32 + 2 * ch] = v;
    }
}

// ---------------------------------------------------------------------------
// LayerNorm over D=256: one warp per row.
// ---------------------------------------------------------------------------
__global__ __launch_bounds__(256) void ln_kernel(
    const float* __restrict__ in, const float* __restrict__ gamma,
    const float* __restrict__ beta, float* __restrict__ out, int rows)
{
    const int lane = threadIdx.x & 31;
    const int row  = blockIdx.x * 8 + (threadIdx.x >> 5);
    if (row >= rows) return;
    const float* p = in + (size_t)row * 256;

    float v[8];
    float s = 0.f;
#pragma unroll
    for (int i = 0; i < 8; i++) { v[i] = p[i * 32 + lane]; s += v[i]; }
#pragma unroll
    for (int o = 16; o > 0; o >>= 1) s += __shfl_xor_sync(0xffffffffu, s, o);
    float mu = s * (1.f / 256.f);

    float vs = 0.f;
#pragma unroll
    for (int i = 0; i < 8; i++) { float d = v[i] - mu; vs += d * d; }
#pragma unroll
    for (int o = 16; o > 0; o >>= 1) vs += __shfl_xor_sync(0xffffffffu, vs, o);
    float rstd = rsqrtf(vs * (1.f / 256.f) + 1e-5f);

    float* q = out + (size_t)row * 256;
#pragma unroll
    for (int i = 0; i < 8; i++) {
        int c = i * 32 + lane;
        q[c] = (v[i] - mu) * rstd * gamma[c] + beta[c];
    }
}

// ---------------------------------------------------------------------------
// Launch
// ---------------------------------------------------------------------------
extern "C" void kernel_launch(void* const* d_in, const int* in_sizes, int n_in,
                              void* d_out, int out_size) {
    const float* src    = (const float*)d_in[0];
    const float* pos    = (const float*)d_in[1];
    const float* refp   = (const float*)d_in[2];
    const float* W_off  = (const float*)d_in[5];
    const float* b_off  = (const float*)d_in[6];
    const float* W_attn = (const float*)d_in[7];
    const float* b_attn = (const float*)d_in[8];
    const float* W_val  = (const float*)d_in[9];
    const float* b_val  = (const float*)d_in[10];
    const float* W_out  = (const float*)d_in[11];
    const float* b_out  = (const float*)d_in[12];
    const float* W_f1   = (const float*)d_in[13];
    const float* b_f1   = (const float*)d_in[14];
    const float* W_f2   = (const float*)d_in[15];
    const float* b_f2   = (const float*)d_in[16];
    const float* ln1g   = (const float*)d_in[17];
    const float* ln1b   = (const float*)d_in[18];
    const float* ln2g   = (const float*)d_in[19];
    const float* ln2b   = (const float*)d_in[20];
    float* out = (float*)d_out;

    float *q, *oa, *acc, *y, *x, *ffn, *y2;
    __half* val;
    float *wtv, *wtoa, *wtu, *wt1, *wt2, *boa;
    cudaGetSymbolAddress((void**)&q,    g_q);
    cudaGetSymbolAddress((void**)&val,  g_val);
    cudaGetSymbolAddress((void**)&oa,   g_oa);
    cudaGetSymbolAddress((void**)&acc,  g_acc);
    cudaGetSymbolAddress((void**)&y,    g_y);
    cudaGetSymbolAddress((void**)&x,    g_x);
    cudaGetSymbolAddress((void**)&ffn,  g_ffn);
    cudaGetSymbolAddress((void**)&y2,   g_y2);
    cudaGetSymbolAddress((void**)&wtv,  g_WT_val);
    cudaGetSymbolAddress((void**)&wtoa, g_WT_oa);
    cudaGetSymbolAddress((void**)&wtu,  g_WT_out);
    cudaGetSymbolAddress((void**)&wt1,  g_WT_f1);
    cudaGetSymbolAddress((void**)&wt2,  g_WT_f2);
    cudaGetSymbolAddress((void**)&boa,  g_b_oa);

    const int DYN = STG * BUF * 2 * 4;   // 81920 B
    cudaFuncSetAttribute(gemm_tc_kernel,
                         cudaFuncAttributeMaxDynamicSharedMemorySize, DYN);

    // 0. all weight transposes (tf32 pre-rounded) + bias concat, one launch
    transpose_all_kernel<<<738, dim3(32, 8)>>>(W_val, W_off, W_attn, W_out,
                                               W_f1, W_f2, b_off, b_attn);

    // 1. q = src + pos
    int n4 = M_TOK * DIM / 4;
    add4_kernel<<<(n4 + 255) / 256, 256>>>((const float4*)src, (const float4*)pos,
                                           (float4*)q, n4);

    dim3 grid256(DIM / 128, M_TOK / 128);   // (2, 340)
    dim3 gridOA(384 / 128, M_TOK / 128);    // (3, 340)
    dim3 gridFFN(DFF / 128, M_TOK / 128);   // (8, 340)

    // 2. value = fp16(src @ W_val + b_val)
    gemm_tc_kernel<<<grid256, 128, DYN>>>(src, wtv, b_val, nullptr, (float*)val,
                                          M_TOK, DIM, DIM, 3);
    // 3. [off | attn logits] = q @ [W_off | W_attn] + [b_off | b_attn]
    gemm_tc_kernel<<<gridOA, 128, DYN>>>(q, wtoa, boa, nullptr, oa,
                                         M_TOK, 384, DIM, 0);
    // 4. deformable sampling (softmax fused) -> acc
    deform_sample_kernel<<<M_TOK * NHEAD / 8, 256>>>(val, oa, refp, acc);

    // 5. y = acc @ W_out + b_out + src
    gemm_tc_kernel<<<grid256, 128, DYN>>>(acc, wtu, b_out, src, y,
                                          M_TOK, DIM, DIM, 2);
    // 6. x = LN1(y)
    ln_kernel<<<M_TOK / 8, 256>>>(y, ln1g, ln1b, x, M_TOK);

    // 7. ffn = relu(x @ W_f1 + b_f1)
    gemm_tc_kernel<<<gridFFN, 128, DYN>>>(x, wt1, b_f1, nullptr, ffn,
                                          M_TOK, DFF, DIM, 1);
    // 8. y2 = ffn @ W_f2 + b_f2 + x
    gemm_tc_kernel<<<grid256, 128, DYN>>>(ffn, wt2, b_f2, x, y2,
                                          M_TOK, DIM, DFF, 2);
    // 9. out = LN2(y2)
    ln_kernel<<<M_TOK / 8, 256>>>(y2, ln2g, ln2b, out, M_TOK);
}

// round 17
// speedup vs baseline: 1.4793x; 1.3211x over previous
#include <cuda_runtime.h>
#include <cuda_fp16.h>
#include <stdint.h>
#include <math.h>

// Problem constants (fixed by setup_inputs)
#define BATCH 2
#define S_TOT 21760
#define DIM 256
#define NHEAD 8
#define NLVL 4
#define NPT 4
#define DFF 1024
#define DHEAD 32
#define M_TOK (BATCH * S_TOT)   // 43520 rows

// ---------------------------------------------------------------------------
// Scratch (device globals — no runtime allocation allowed)
// ---------------------------------------------------------------------------
__device__ __half g_src16[M_TOK * DIM];   // fp16 copy of src (value GEMM A)
__device__ __half g_q16  [M_TOK * DIM];   // fp16 q = src + pos (OA GEMM A)
__device__ __half g_val  [M_TOK * DIM];   // fp16 value tensor
__device__ float  g_oa   [M_TOK * 384];   // offsets(256) + attn logits(128)
__device__ __half g_acc16[M_TOK * DIM];   // fp16 sampler output (out GEMM A)
__device__ float  g_y    [M_TOK * DIM];
__device__ float  g_x    [M_TOK * DIM];   // LN1 out fp32 (residual for ffn2)
__device__ __half g_x16  [M_TOK * DIM];   // LN1 out fp16 (ffn1 GEMM A)
__device__ __half g_ffn16[M_TOK * DFF];   // fp16 relu(ffn1) (ffn2 GEMM A)
__device__ float  g_y2   [M_TOK * DIM];

// Transposed (K-major) fp16 weights: WT[n*K + k] = fp16(W[k*N + n])
__device__ __half g_WT_val [DIM * DIM];
__device__ __half g_WT_oa  [384 * DIM];
__device__ __half g_WT_out [DIM * DIM];
__device__ __half g_WT_f1  [DFF * DIM];
__device__ __half g_WT_f2  [DIM * DFF];
__device__ float  g_b_oa   [384];

__device__ __forceinline__ uint32_t smem_u32(const void* p) {
    uint32_t a;
    asm("{ .reg .u64 t; cvta.to.shared.u64 t, %1; cvt.u32.u64 %0, t; }"
        : "=r"(a) : "l"(p));
    return a;
}

// ---------------------------------------------------------------------------
// One launch: all weight transposes (fp32 -> fp16 K-major) + bias concat.
// ---------------------------------------------------------------------------
__global__ void transpose_all_kernel(
    const float* __restrict__ W_val, const float* __restrict__ W_off,
    const float* __restrict__ W_attn, const float* __restrict__ W_out,
    const float* __restrict__ W_f1,  const float* __restrict__ W_f2,
    const float* __restrict__ b_off, const float* __restrict__ b_attn)
{
    const int bid = blockIdx.x;
    const int tx = threadIdx.x, ty0 = threadIdx.y;

    if (bid >= 736) {   // bias concat blocks (736, 737)
        int idx = (bid - 736) * 256 + ty0 * 32 + tx;
        if (idx < 384)
            g_b_oa[idx] = (idx < 256) ? b_off[idx] : b_attn[idx - 256];
        return;
    }

    const float* W; __half* WT; int K, N, lt;
    if      (bid < 64)  { W = W_val;  WT = g_WT_val;            K = 256;  N = 256;  lt = bid; }
    else if (bid < 128) { W = W_off;  WT = g_WT_oa;             K = 256;  N = 256;  lt = bid - 64; }
    else if (bid < 160) { W = W_attn; WT = g_WT_oa + 256 * 256; K = 256;  N = 128;  lt = bid - 128; }
    else if (bid < 224) { W = W_out;  WT = g_WT_out;            K = 256;  N = 256;  lt = bid - 160; }
    else if (bid < 480) { W = W_f1;   WT = g_WT_f1;             K = 256;  N = 1024; lt = bid - 224; }
    else                { W = W_f2;   WT = g_WT_f2;             K = 1024; N = 256;  lt = bid - 480; }

    const int tiles_x = N >> 5;
    const int bn = (lt % tiles_x) * 32;
    const int bk = (lt / tiles_x) * 32;

    __shared__ float tile[32][33];
#pragma unroll
    for (int i = 0; i < 4; i++) {
        int ty = ty0 + i * 8;
        tile[ty][tx] = W[(size_t)(bk + ty) * N + bn + tx];
    }
    __syncthreads();
#pragma unroll
    for (int i = 0; i < 4; i++) {
        int ty = ty0 + i * 8;
        WT[(size_t)(bn + ty) * K + bk + tx] = __float2half(tile[tx][ty]);
    }
}

// ---------------------------------------------------------------------------
// fp16 mma.sync (m16n8k16) GEMM, cp.async 4-stage pipeline.
// C[M,N] = A[M,K] @ WT[N,K]^T + bias, fp32 accumulate.
// BM=BN=128, BK=32, 128 threads (4 warps, 2x2), warp tile 64x64.
// fuse: 0 fp32, 1 relu fp32, 2 +res fp32, 3 fp16 out, 4 relu + fp16 out
// ---------------------------------------------------------------------------
#define SMSH 40                 // smem row stride in halves (80B = 20 banks)
#define STG 4
#define BUFH (128 * SMSH)       // halves per operand per stage

__global__ __launch_bounds__(128, 2) void gemm_fp16_kernel(
    const __half* __restrict__ A, const __half* __restrict__ WT,
    const float* __restrict__ bias, const float* __restrict__ res,
    float* __restrict__ C, int M, int N, int K, int fuse)
{
    extern __shared__ __half smh[];
    __half* sA = smh;                 // STG * BUFH halves
    __half* sB = smh + STG * BUFH;    // STG * BUFH halves

    const int t    = threadIdx.x;   // 0..127
    const int wid  = t >> 5;        // 0..3
    const int lane = t & 31;
    const int wm   = (wid >> 1) * 64;
    const int wn   = (wid & 1) * 64;
    const int bm   = blockIdx.y * 128;
    const int bn   = blockIdx.x * 128;

    const __half* Ab = A  + (size_t)bm * K;
    const __half* Bb = WT + (size_t)bn * K;

    float acc[4][8][4];
#pragma unroll
    for (int i = 0; i < 4; i++)
#pragma unroll
        for (int j = 0; j < 8; j++)
#pragma unroll
            for (int e = 0; e < 4; e++) acc[i][j][e] = 0.f;

    const int nch = K >> 5;   // K chunks of 32

    // copy units: 512 x 16B (8 halves) per operand tile; 4 per thread each
    auto issue = [&](int c) {
        const int s = c % STG;
        __half* a = sA + s * BUFH;
        __half* b = sB + s * BUFH;
        const int kb = c << 5;
#pragma unroll
        for (int i = 0; i < 4; i++) {
            int u   = t + (i << 7);        // 0..511
            int row = u >> 2;
            int seg = (u & 3) << 3;        // halves
            uint32_t d;
            d = smem_u32(a + row * SMSH + seg);
            asm volatile("cp.async.ca.shared.global [%0], [%1], 16;"
                         :: "r"(d), "l"(Ab + (size_t)row * K + kb + seg) : "memory");
            d = smem_u32(b + row * SMSH + seg);
            asm volatile("cp.async.ca.shared.global [%0], [%1], 16;"
                         :: "r"(d), "l"(Bb + (size_t)row * K + kb + seg) : "memory");
        }
        asm volatile("cp.async.commit_group;" ::: "memory");
    };

    const int lr = lane >> 2;   // 0..7
    const int lk = lane & 3;    // 0..3

    auto compute = [&](int c) {
        const int s = c % STG;
        const __half* a  = sA + s * BUFH;
        const __half* bp = sB + s * BUFH;
#pragma unroll
        for (int ks = 0; ks < 32; ks += 16) {
            uint32_t af[4][4], bf[8][2];
#pragma unroll
            for (int mt = 0; mt < 4; mt++) {
                int mr = wm + mt * 16 + lr;
                const __half* p0 = a + mr * SMSH + ks + lk * 2;
                const __half* p1 = a + (mr + 8) * SMSH + ks + lk * 2;
                af[mt][0] = *(const uint32_t*)p0;
                af[mt][1] = *(const uint32_t*)p1;
                af[mt][2] = *(const uint32_t*)(p0 + 8);
                af[mt][3] = *(const uint32_t*)(p1 + 8);
            }
#pragma unroll
            for (int nt = 0; nt < 8; nt++) {
                int nc = wn + nt * 8 + lr;
                const __half* p = bp + nc * SMSH + ks + lk * 2;
                bf[nt][0] = *(const uint32_t*)p;
                bf[nt][1] = *(const uint32_t*)(p + 8);
            }
#pragma unroll
            for (int mt = 0; mt < 4; mt++)
#pragma unroll
                for (int nt = 0; nt < 8; nt++) {
                    asm volatile(
                        "mma.sync.aligned.m16n8k16.row.col.f32.f16.f16.f32 "
                        "{%0,%1,%2,%3}, {%4,%5,%6,%7}, {%8,%9}, {%0,%1,%2,%3};"
                        : "+f"(acc[mt][nt][0]), "+f"(acc[mt][nt][1]),
                          "+f"(acc[mt][nt][2]), "+f"(acc[mt][nt][3])
                        : "r"(af[mt][0]), "r"(af[mt][1]),
                          "r"(af[mt][2]), "r"(af[mt][3]),
                          "r"(bf[nt][0]), "r"(bf[nt][1]));
                }
        }
    };

    issue(0);
    if (nch > 1) issue(1);
    if (nch > 2) issue(2);

    for (int c = 0; c < nch; c++) {
        asm volatile("cp.async.wait_group 2;" ::: "memory");
        __syncthreads();
        if (c + 3 < nch) issue(c + 3);
        compute(c);
    }

    // ---- epilogue ----
    const int cL = (lane & 3) * 2;
#pragma unroll
    for (int mt = 0; mt < 4; mt++) {
        int row = bm + wm + mt * 16 + lr;
#pragma unroll
        for (int nt = 0; nt < 8; nt++) {
            int col = bn + wn + nt * 8 + cL;
            float2 v0, v1;
            v0.x = acc[mt][nt][0] + bias[col];
            v0.y = acc[mt][nt][1] + bias[col + 1];
            v1.x = acc[mt][nt][2] + bias[col];
            v1.y = acc[mt][nt][3] + bias[col + 1];
            if (fuse == 1 || fuse == 4) {
                v0.x = fmaxf(v0.x, 0.f); v0.y = fmaxf(v0.y, 0.f);
                v1.x = fmaxf(v1.x, 0.f); v1.y = fmaxf(v1.y, 0.f);
            } else if (fuse == 2) {
                float2 r0v = *(const float2*)&res[(size_t)row * N + col];
                float2 r1v = *(const float2*)&res[(size_t)(row + 8) * N + col];
                v0.x += r0v.x; v0.y += r0v.y;
                v1.x += r1v.x; v1.y += r1v.y;
            }
            if (fuse >= 3) {
                __half* Ch = (__half*)C;
                *(__half2*)&Ch[(size_t)row * N + col] =
                    __floats2half2_rn(v0.x, v0.y);
                *(__half2*)&Ch[(size_t)(row + 8) * N + col] =
                    __floats2half2_rn(v1.x, v1.y);
            } else {
                *(float2*)&C[(size_t)row * N + col] = v0;
                *(float2*)&C[(size_t)(row + 8) * N + col] = v1;
            }
        }
    }
}

// ---------------------------------------------------------------------------
// q16 = fp16(src + pos), src16 = fp16(src)
// ---------------------------------------------------------------------------
__global__ void add4_kernel(const float4* __restrict__ a,
                            const float4* __restrict__ b,
                            __half2* __restrict__ q16,
                            __half2* __restrict__ s16, int n4) {
    int i = blockIdx.x * blockDim.x + threadIdx.x;
    if (i < n4) {
        float4 x = a[i], y = b[i];
        q16[2 * i]     = __floats2half2_rn(x.x + y.x, x.y + y.y);
        q16[2 * i + 1] = __floats2half2_rn(x.z + y.z, x.w + y.w);
        s16[2 * i]     = __floats2half2_rn(x.x, x.y);
        s16[2 * i + 1] = __floats2half2_rn(x.z, x.w);
    }
}

// ---------------------------------------------------------------------------
// Deformable sampling, half-warp parallel, __half2 gathers, fused softmax.
// One warp per (token, head). Lane = half2 channel pair (16 lanes = 32 ch).
// Output written as fp16 (feeds the out-projection GEMM).
// ---------------------------------------------------------------------------
__global__ __launch_bounds__(256) void deform_sample_kernel(
    const __half* __restrict__ value, const float* __restrict__ oa,
    const float* __restrict__ refp, __half2* __restrict__ out16)
{
    const int lane = threadIdx.x & 31;
    const int wid  = blockIdx.x * 8 + (threadIdx.x >> 5);
    const int tok = wid >> 3;
    const int h   = wid & 7;
    const int b   = tok / S_TOT;
    const int hw  = lane >> 4;    // half-warp id
    const int ch  = lane & 15;    // half2 channel index

    float offv  = oa[(size_t)tok * 384 + h * 32 + lane];
    float logit = (lane < 16) ? oa[(size_t)tok * 384 + 256 + h * 16 + lane] : -1e30f;
    float refv  = (lane < 8)  ? refp[(size_t)tok * 8 + lane] : 0.f;

    // softmax over 16 logits held in lanes 0..15
    float m = logit;
#pragma unroll
    for (int o = 8; o > 0; o >>= 1) m = fmaxf(m, __shfl_xor_sync(0xffffffffu, m, o));
    float e = (lane < 16) ? expf(logit - m) : 0.f;
    float ssum = e;
#pragma unroll
    for (int o = 8; o > 0; o >>= 1) ssum += __shfl_xor_sync(0xffffffffu, ssum, o);
    float attnv = e / ssum;

    const __half2* vb =
        (const __half2*)(value + (size_t)b * S_TOT * 256 + h * 32) + ch;

    float accx = 0.f, accy = 0.f;
#pragma unroll
    for (int s = 0; s < 8; s++) {
        const int ls = s >> 2;            // compile-time 0/1
        const int l  = hw * 2 + ls;       // per-lane level
        const int j  = hw * 8 + s;        // per-lane sample index
        const int Wl = 128 >> l;
        const float fW = (float)Wl;
        const int start = hw ? (ls ? 21504 : 20480) : (ls ? 16384 : 0);

        float rx = __shfl_sync(0xffffffffu, refv, 2 * l);
        float ry = __shfl_sync(0xffffffffu, refv, 2 * l + 1);
        float ox = __shfl_sync(0xffffffffu, offv, 2 * j);
        float oy = __shfl_sync(0xffffffffu, offv, 2 * j + 1);
        float aw = __shfl_sync(0xffffffffu, attnv, j);

        float locx = rx + ox / fW;
        float locy = ry + oy / fW;
        float x = locx * fW - 0.5f;
        float y = locy * fW - 0.5f;
        float x0f = floorf(x), y0f = floorf(y);
        float wx = x - x0f, wy = y - y0f;
        int x0 = (int)x0f, y0 = (int)y0f;
        int x1 = x0 + 1,   y1 = y0 + 1;

        bool vx0 = (x0 >= 0) && (x0 < Wl);
        bool vx1 = (x1 >= 0) && (x1 < Wl);
        bool vy0 = (y0 >= 0) && (y0 < Wl);
        bool vy1 = (y1 >= 0) && (y1 < Wl);

        int x0c = min(max(x0, 0), Wl - 1);
        int x1c = min(max(x1, 0), Wl - 1);
        int y0c = min(max(y0, 0), Wl - 1);
        int y1c = min(max(y1, 0), Wl - 1);

        float w00 = (vx0 && vy0) ? (1.f - wx) * (1.f - wy) * aw : 0.f;
        float w01 = (vx1 && vy0) ? wx * (1.f - wy) * aw : 0.f;
        float w10 = (vx0 && vy1) ? (1.f - wx) * wy * aw : 0.f;
        float w11 = (vx1 && vy1) ? wx * wy * aw : 0.f;

        const __half2* vl = vb + (size_t)start * 128;
        float2 f00 = __half22float2(vl[(size_t)(y0c * Wl + x0c) * 128]);
        float2 f01 = __half22float2(vl[(size_t)(y0c * Wl + x1c) * 128]);
        float2 f10 = __half22float2(vl[(size_t)(y1c * Wl + x0c) * 128]);
        float2 f11 = __half22float2(vl[(size_t)(y1c * Wl + x1c) * 128]);

        accx += w00 * f00.x + w01 * f01.x + w10 * f10.x + w11 * f11.x;
        accy += w00 * f00.y + w01 * f01.y + w10 * f10.y + w11 * f11.y;
    }

    accx += __shfl_xor_sync(0xffffffffu, accx, 16);
    accy += __shfl_xor_sync(0xffffffffu, accy, 16);

    if (lane < 16)
        out16[(size_t)tok * 128 + h * 16 + ch] = __floats2half2_rn(accx, accy);
}

// ---------------------------------------------------------------------------
// LayerNorm over D=256: one warp per row; optional fp16 dual output.
// ---------------------------------------------------------------------------
__global__ __launch_bounds__(256) void ln_kernel(
    const float* __restrict__ in, const float* __restrict__ gamma,
    const float* __restrict__ beta, float* __restrict__ out,
    __half* __restrict__ out16, int rows)
{
    const int lane = threadIdx.x & 31;
    const int row  = blockIdx.x * 8 + (threadIdx.x >> 5);
    if (row >= rows) return;
    const float* p = in + (size_t)row * 256;

    float v[8];
    float s = 0.f;
#pragma unroll
    for (int i = 0; i < 8; i++) { v[i] = p[i * 32 + lane]; s += v[i]; }
#pragma unroll
    for (int o = 16; o > 0; o >>= 1) s += __shfl_xor_sync(0xffffffffu, s, o);
    float mu = s * (1.f / 256.f);

    float vs = 0.f;
#pragma unroll
    for (int i = 0; i < 8; i++) { float d = v[i] - mu; vs += d * d; }
#pragma unroll
    for (int o = 16; o > 0; o >>= 1) vs += __shfl_xor_sync(0xffffffffu, vs, o);
    float rstd = rsqrtf(vs * (1.f / 256.f) + 1e-5f);

    float* q = out + (size_t)row * 256;
#pragma unroll
    for (int i = 0; i < 8; i++) {
        int c = i * 32 + lane;
        float r = (v[i] - mu) * rstd * gamma[c] + beta[c];
        q[c] = r;
        if (out16) out16[(size_t)row * 256 + c] = __float2half(r);
    }
}

// ---------------------------------------------------------------------------
// Launch
// ---------------------------------------------------------------------------
extern "C" void kernel_launch(void* const* d_in, const int* in_sizes, int n_in,
                              void* d_out, int out_size) {
    const float* src    = (const float*)d_in[0];
    const float* pos    = (const float*)d_in[1];
    const float* refp   = (const float*)d_in[2];
    const float* W_off  = (const float*)d_in[5];
    const float* b_off  = (const float*)d_in[6];
    const float* W_attn = (const float*)d_in[7];
    const float* b_attn = (const float*)d_in[8];
    const float* W_val  = (const float*)d_in[9];
    const float* b_val  = (const float*)d_in[10];
    const float* W_out  = (const float*)d_in[11];
    const float* b_out  = (const float*)d_in[12];
    const float* W_f1   = (const float*)d_in[13];
    const float* b_f1   = (const float*)d_in[14];
    const float* W_f2   = (const float*)d_in[15];
    const float* b_f2   = (const float*)d_in[16];
    const float* ln1g   = (const float*)d_in[17];
    const float* ln1b   = (const float*)d_in[18];
    const float* ln2g   = (const float*)d_in[19];
    const float* ln2b   = (const float*)d_in[20];
    float* out = (float*)d_out;

    __half *s16, *q16, *val, *acc16, *x16, *ffn16;
    float *oa, *y, *x, *y2, *boa;
    __half *wtv, *wtoa, *wtu, *wt1, *wt2;
    cudaGetSymbolAddress((void**)&s16,   g_src16);
    cudaGetSymbolAddress((void**)&q16,   g_q16);
    cudaGetSymbolAddress((void**)&val,   g_val);
    cudaGetSymbolAddress((void**)&oa,    g_oa);
    cudaGetSymbolAddress((void**)&acc16, g_acc16);
    cudaGetSymbolAddress((void**)&y,     g_y);
    cudaGetSymbolAddress((void**)&x,     g_x);
    cudaGetSymbolAddress((void**)&x16,   g_x16);
    cudaGetSymbolAddress((void**)&ffn16, g_ffn16);
    cudaGetSymbolAddress((void**)&y2,    g_y2);
    cudaGetSymbolAddress((void**)&wtv,   g_WT_val);
    cudaGetSymbolAddress((void**)&wtoa,  g_WT_oa);
    cudaGetSymbolAddress((void**)&wtu,   g_WT_out);
    cudaGetSymbolAddress((void**)&wt1,   g_WT_f1);
    cudaGetSymbolAddress((void**)&wt2,   g_WT_f2);
    cudaGetSymbolAddress((void**)&boa,   g_b_oa);

    const int DYN = STG * BUFH * 2 * 2;   // 81920 B
    cudaFuncSetAttribute(gemm_fp16_kernel,
                         cudaFuncAttributeMaxDynamicSharedMemorySize, DYN);

    // 0. all weight transposes (fp16 K-major) + bias concat, one launch
    transpose_all_kernel<<<738, dim3(32, 8)>>>(W_val, W_off, W_attn, W_out,
                                               W_f1, W_f2, b_off, b_attn);

    // 1. q16 = fp16(src + pos), src16 = fp16(src)
    int n4 = M_TOK * DIM / 4;
    add4_kernel<<<(n4 + 255) / 256, 256>>>((const float4*)src, (const float4*)pos,
                                           (__half2*)q16, (__half2*)s16, n4);

    dim3 grid256(DIM / 128, M_TOK / 128);   // (2, 340)
    dim3 gridOA(384 / 128, M_TOK / 128);    // (3, 340)
    dim3 gridFFN(DFF / 128, M_TOK / 128);   // (8, 340)

    // 2. value = fp16(src @ W_val + b_val)
    gemm_fp16_kernel<<<grid256, 128, DYN>>>(s16, wtv, b_val, nullptr, (float*)val,
                                            M_TOK, DIM, DIM, 3);
    // 3. [off | attn logits] = q @ [W_off | W_attn] + [b_off | b_attn]
    gemm_fp16_kernel<<<gridOA, 128, DYN>>>(q16, wtoa, boa, nullptr, oa,
                                           M_TOK, 384, DIM, 0);
    // 4. deformable sampling (softmax fused) -> acc16
    deform_sample_kernel<<<M_TOK * NHEAD / 8, 256>>>(val, oa, refp,
                                                     (__half2*)acc16);
    // 5. y = acc @ W_out + b_out + src
    gemm_fp16_kernel<<<grid256, 128, DYN>>>(acc16, wtu, b_out, src, y,
                                            M_TOK, DIM, DIM, 2);
    // 6. x = LN1(y), x16 = fp16(x)
    ln_kernel<<<M_TOK / 8, 256>>>(y, ln1g, ln1b, x, x16, M_TOK);

    // 7. ffn16 = fp16(relu(x @ W_f1 + b_f1))
    gemm_fp16_kernel<<<gridFFN, 128, DYN>>>(x16, wt1, b_f1, nullptr, (float*)ffn16,
                                            M_TOK, DFF, DIM, 4);
    // 8. y2 = ffn @ W_f2 + b_f2 + x
    gemm_fp16_kernel<<<grid256, 128, DYN>>>(ffn16, wt2, b_f2, x, y2,
                                            M_TOK, DIM, DFF, 2);
    // 9. out = LN2(y2)
    ln_kernel<<<M_TOK / 8, 256>>>(y2, ln2g, ln2b, out, nullptr, M_TOK);
}